// round 1
// baseline (speedup 1.0000x reference)
#include <cuda_runtime.h>

#define BB 64
#define NN 2048
#define MM 256
#define NSPLIT 32
#define ROWS_PER_CHUNK (NN / NSPLIT)   // 64 rows per pass-3 block

// ---- scratch (static __device__ globals; no allocation) ----
__device__ float2 g_dots[BB * NN];              // (dot, sumsq) per memory row   1 MB
__device__ float  g_c[BB * NN];                 // w_r * (1 - w_lu_prev)         512 KB
__device__ float  g_s[BB];                      // sum_n w_r * w_w
__device__ float  g_partial[NSPLIT * BB * MM];  // pass-3 partials               2 MB

// ============================================================================
// Pass 1: per-row dot(mem_row, k) and sum-of-squares. Warp per row.
// grid = B*N/8 blocks (16384), block = 256 (8 warps). Ascending address order.
// ============================================================================
__global__ void k_pass1(const float* __restrict__ mem, const float* __restrict__ k)
{
    __shared__ float4 sk[MM / 4];
    const int bidx = blockIdx.x;         // 256 blocks per batch (2048 rows / 8)
    const int b = bidx >> 8;
    const int t = threadIdx.x;
    if (t < MM / 4) sk[t] = reinterpret_cast<const float4*>(k + (size_t)b * MM)[t];
    __syncthreads();

    const int warp = t >> 5, lane = t & 31;
    const size_t row = (size_t)bidx * 8 + warp;
    const float4* mr = reinterpret_cast<const float4*>(mem + row * MM);

    float4 v0 = mr[lane];
    float4 v1 = mr[lane + 32];
    float4 k0 = sk[lane];
    float4 k1 = sk[lane + 32];

    float dot = v0.x * k0.x + v0.y * k0.y + v0.z * k0.z + v0.w * k0.w
              + v1.x * k1.x + v1.y * k1.y + v1.z * k1.z + v1.w * k1.w;
    float ss  = v0.x * v0.x + v0.y * v0.y + v0.z * v0.z + v0.w * v0.w
              + v1.x * v1.x + v1.y * v1.y + v1.z * v1.z + v1.w * v1.w;

    #pragma unroll
    for (int off = 16; off > 0; off >>= 1) {
        dot += __shfl_down_sync(0xffffffffu, dot, off);
        ss  += __shfl_down_sync(0xffffffffu, ss,  off);
    }
    if (lane == 0) g_dots[row] = make_float2(dot, ss);
}

// ============================================================================
// Block-wide reduction for 256 threads (sum or max), result broadcast to all.
// ============================================================================
template <bool IS_MAX>
__device__ __forceinline__ float block_reduce256(float v)
{
    __shared__ float sh[8];
    const int lane = threadIdx.x & 31, warp = threadIdx.x >> 5;
    #pragma unroll
    for (int off = 16; off > 0; off >>= 1) {
        float o = __shfl_down_sync(0xffffffffu, v, off);
        v = IS_MAX ? fmaxf(v, o) : (v + o);
    }
    if (lane == 0) sh[warp] = v;
    __syncthreads();
    float r;
    if (threadIdx.x == 0) {
        r = sh[0];
        #pragma unroll
        for (int i = 1; i < 8; i++) r = IS_MAX ? fmaxf(r, sh[i]) : (r + sh[i]);
        sh[0] = r;
    }
    __syncthreads();
    r = sh[0];
    __syncthreads();   // sh is reused by subsequent calls
    return r;
}

// ============================================================================
// Pass 2: cosine similarity + softmax + fold in w_prev / w_lu_prev.
// One block (256 threads) per batch; 8 n-elements per thread.
// Produces g_c[b,n] = w_r*(1-w_lu_prev)  and  g_s[b] = sum w_r*w_w.
// NOTE: w_u / sort / w_lu / gamma are dead code w.r.t. the output -> skipped.
// ============================================================================
__global__ void k_pass2(const float* __restrict__ k, const float* __restrict__ g,
                        const float* __restrict__ w_prev, const int* __restrict__ w_lu_prev)
{
    const int b = blockIdx.x;
    const int t = threadIdx.x;

    // ||k_b||
    float kv = k[(size_t)b * MM + t];
    float ksum = block_reduce256<false>(kv * kv);
    float knrm = fmaxf(sqrtf(ksum), 1e-8f);

    // cosine per owned element, track max
    float cosv[8];
    float mx = -1e30f;
    #pragma unroll
    for (int i = 0; i < 8; i++) {
        float2 d = g_dots[(size_t)b * NN + t + i * 256];
        float nrm = fmaxf(sqrtf(d.y), 1e-8f);
        float cv = d.x / (nrm * knrm);
        cosv[i] = cv;
        mx = fmaxf(mx, cv);
    }
    float gmx = block_reduce256<true>(mx);

    float ex[8];
    float lsum = 0.f;
    #pragma unroll
    for (int i = 0; i < 8; i++) {
        ex[i] = __expf(cosv[i] - gmx);
        lsum += ex[i];
    }
    float S = block_reduce256<false>(lsum);
    float inv = 1.f / S;

    const float gb = g[b];
    float sacc = 0.f;
    #pragma unroll
    for (int i = 0; i < 8; i++) {
        int n = t + i * 256;
        float wr  = ex[i] * inv;
        float wrp = w_prev[((size_t)b * 2 + 1) * NN + n];   // w_r_prev = w_prev[:,1,:]
        float wlu = (float)w_lu_prev[(size_t)b * NN + n];
        float ww  = gb * wrp + (1.f - gb) * wlu;
        g_c[(size_t)b * NN + n] = wr * (1.f - wlu);
        sacc += wr * ww;
    }
    float stot = block_reduce256<false>(sacc);
    if (t == 0) g_s[b] = stot;
}

// ============================================================================
// Pass 3: partial[split][b][m] = sum over 64 rows of c[b,n]*mem[b,n,m].
// Blocks mapped in REVERSE address order so the tail of pass 1's L2 stream
// is hit instead of sweep-thrashed. 256 threads: 4 row-subgroups x 64 float4
// columns. Deterministic (no atomics).
// ============================================================================
__global__ void k_pass3(const float* __restrict__ mem)
{
    const int chunk = (int)gridDim.x - 1 - (int)blockIdx.x;   // reversed mapping
    const int b  = chunk >> 5;            // chunk / NSPLIT
    const int sp = chunk & (NSPLIT - 1);
    const int row0 = sp * ROWS_PER_CHUNK;

    __shared__ float  sc[ROWS_PER_CHUNK];
    __shared__ float4 red[4][MM / 4];

    const int t = threadIdx.x;
    if (t < ROWS_PER_CHUNK) sc[t] = g_c[(size_t)b * NN + row0 + t];
    __syncthreads();

    const int sub = t >> 6;       // 0..3 : row subgroup
    const int q   = t & 63;       // float4 column
    const float4* mrow = reinterpret_cast<const float4*>(
        mem + ((size_t)b * NN + row0) * MM);

    float4 acc = make_float4(0.f, 0.f, 0.f, 0.f);
    #pragma unroll
    for (int it = ROWS_PER_CHUNK / 4 - 1; it >= 0; --it) {   // descending rows
        int rl = it * 4 + sub;
        float c = sc[rl];
        float4 v = mrow[(size_t)rl * (MM / 4) + q];
        acc.x += c * v.x; acc.y += c * v.y; acc.z += c * v.z; acc.w += c * v.w;
    }

    red[sub][q] = acc;
    __syncthreads();
    if (sub == 0) {
        float4 a0 = red[0][q], a1 = red[1][q], a2 = red[2][q], a3 = red[3][q];
        float4 s;
        s.x = a0.x + a1.x + a2.x + a3.x;
        s.y = a0.y + a1.y + a2.y + a3.y;
        s.z = a0.z + a1.z + a2.z + a3.z;
        s.w = a0.w + a1.w + a2.w + a3.w;
        reinterpret_cast<float4*>(g_partial)[((size_t)sp * BB + b) * (MM / 4) + q] = s;
    }
}

// ============================================================================
// Pass 4: out[b,m] = sum_sp partial[sp][b][m] + s[b]*k[b,m]
// ============================================================================
__global__ void k_final(const float* __restrict__ k, float* __restrict__ out)
{
    const int idx = blockIdx.x * 256 + threadIdx.x;   // b*M + m, 16384 total
    const int b = idx >> 8;
    float acc = 0.f;
    #pragma unroll
    for (int sp = 0; sp < NSPLIT; sp++)
        acc += g_partial[((size_t)sp * BB + b) * MM + (idx & 255)];
    out[idx] = acc + g_s[b] * k[idx];
}

// ============================================================================
extern "C" void kernel_launch(void* const* d_in, const int* in_sizes, int n_in,
                              void* d_out, int out_size)
{
    const float* mem       = (const float*)d_in[0];   // (64,2048,256) f32
    const float* k         = (const float*)d_in[1];   // (64,256) f32
    const float* g         = (const float*)d_in[2];   // (64,1) f32
    // d_in[3] gamma: unused (dead code w.r.t. output)
    const float* w_prev    = (const float*)d_in[4];   // (64,2,2048) f32
    const int*   w_lu_prev = (const int*)d_in[5];     // (64,2048) i32
    // d_in[6] n: unused (sort/w_lu are dead code)
    float* out = (float*)d_out;                       // (64,256) f32

    k_pass1<<<(BB * NN) / 8, 256>>>(mem, k);
    k_pass2<<<BB, 256>>>(k, g, w_prev, w_lu_prev);
    k_pass3<<<BB * NSPLIT, 256>>>(mem);
    k_final<<<(BB * MM) / 256, 256>>>(k, out);
}